// round 9
// baseline (speedup 1.0000x reference)
#include <cuda_runtime.h>

// FourierAttention1d — linear attention, reassociated + output-projection folded.
//   KV[b,h,d,e] = sum_n LN(v Wk^T + kb)[n,h,d] * (v Wv^T + vb)[n,h,e]
//   G[b,h,d,c]  = sum_e KV[b,h,d,e] * o_w[c, h*64+e]
//   out[b,n,c]  = ( sum_{h,d} LN(v Wq^T + qb)[n,h,d] * G[b,h,d,c] + o_b[c] ) / N
//
// R8 resubmit (infra timeout): 8x8 per-thread tiles, FFMA2 packed over output
// dims, zero_kv grid covers all 131072 elements (determinism fix from R7).

#define B_   4
#define N_   8192
#define H_   8
#define HD_  512

typedef unsigned long long u64;

__device__ float g_KV[B_ * H_ * 4096];   // [b][h][d][e]
__device__ float g_G [B_ * H_ * 4096];   // [b][h][d][c]

__global__ void zero_kv_kernel() {
    int i = blockIdx.x * blockDim.x + threadIdx.x;
    if (i < B_ * H_ * 4096) g_KV[i] = 0.0f;
}

__device__ __forceinline__ void ffma2(u64& d, u64 a, u64 b) {
    asm("fma.rn.f32x2 %0, %1, %2, %3;" : "=l"(d) : "l"(a), "l"(b), "l"(d));
}
__device__ __forceinline__ u64 dup2(float x) {
    u64 r; asm("mov.b64 %0, {%1, %1};" : "=l"(r) : "f"(x)); return r;
}
__device__ __forceinline__ u64 pk2(float a, float b) {
    u64 r; asm("mov.b64 %0, {%1, %2};" : "=l"(r) : "f"(a), "f"(b)); return r;
}
__device__ __forceinline__ void up2(u64 p, float& a, float& b) {
    asm("mov.b64 {%0, %1}, %2;" : "=f"(a), "=f"(b) : "l"(p));
}
__device__ __forceinline__ void add2(u64& d, u64 a) {
    asm("add.rn.f32x2 %0, %1, %2;" : "=l"(d) : "l"(d), "l"(a));
}

// ---------------------------------------------------------------------------
// Kernel 1: grid (4 chunks, H, B) = 128 blocks, 256 thr, 2048 tokens/block.
// smem (floats): sWkT[64c][66] @0 | sWvT @4228 | sV[128t][68] @8452 |
//   sK[128t][68] @17156 | sU @25864 | sKb @34568 sVb @34632 sLw @34696 sLb @34760
// ---------------------------------------------------------------------------
#define KV_SMEM_F 34824
#define KV_SMEM_BYTES (KV_SMEM_F * 4)

__global__ __launch_bounds__(256, 1) void kv_kernel(
    const float* __restrict__ v,
    const float* __restrict__ Wk, const float* __restrict__ kb,
    const float* __restrict__ Wv, const float* __restrict__ vb,
    const float* __restrict__ lnw, const float* __restrict__ lnb)
{
    extern __shared__ float sm[];
    float* sWkT = sm;           // [c][66], d contiguous (pairs)
    float* sWvT = sm + 4228;    // offset delta 4228 ≡ 4 (mod 8) -> bank interleave
    float* sV   = sm + 8452;    // [t][68]
    float* sK   = sm + 17156;   // [t][68] LN'd K
    float* sU   = sm + 25864;   // [t][68]
    float* sKb  = sm + 34568;
    float* sVb  = sm + 34632;
    float* sLw  = sm + 34696;
    float* sLb  = sm + 34760;

    const int chunk = blockIdx.x, h = blockIdx.y, b = blockIdx.z;
    const int tid = threadIdx.x;
    const int ty = tid >> 4, tx = tid & 15;
    const bool isK = tx < 8;
    const int d0 = (tx & 7) * 8;

    for (int i = tid; i < 4096; i += 256) {
        int d = i >> 6, c = i & 63;
        sWkT[c * 66 + d] = Wk[(h * 64 + d) * 64 + c];
        sWvT[c * 66 + d] = Wv[(h * 64 + d) * 64 + c];
    }
    if (tid < 64) {
        sKb[tid] = kb[h * 64 + tid];
        sVb[tid] = vb[h * 64 + tid];
        sLw[tid] = lnw[h * 64 + tid];
        sLb[tid] = lnb[h * 64 + tid];
    }
    __syncthreads();

    const float* Wb = isK ? sWkT : sWvT;
    const float* bb = isK ? sKb : sVb;
    u64 biasP[4];
    float lw8[8], lb8[8];
    #pragma unroll
    for (int j = 0; j < 4; j++) biasP[j] = *(const u64*)&bb[d0 + 2 * j];
    #pragma unroll
    for (int k = 0; k < 8; k++) { lw8[k] = sLw[d0 + k]; lb8[k] = sLb[d0 + k]; }

    // outer-product ownership
    const int g = tid >> 6, gy = (tid >> 3) & 7, gx = tid & 7;
    u64 kvacc[8][4];
    #pragma unroll
    for (int i = 0; i < 8; i++)
        #pragma unroll
        for (int j = 0; j < 4; j++) kvacc[i][j] = 0ull;

    const int n_base = b * N_ + chunk * 2048;

    for (int t0 = 0; t0 < 2048; t0 += 128) {
        // fill v tile [128][64]
        for (int i = tid; i < 2048; i += 256) {
            int t = i >> 4, c4 = (i & 15) * 4;
            *(float4*)&sV[t * 68 + c4] = *(const float4*)&v[(n_base + t0 + t) * 64 + c4];
        }
        __syncthreads();

        // ---- proj: thread = tokens ty*8..+7, dims d0..d0+7 of K (tx<8) or U
        u64 acc[8][4];
        #pragma unroll
        for (int i = 0; i < 8; i++)
            #pragma unroll
            for (int j = 0; j < 4; j++) acc[i][j] = 0ull;

        #pragma unroll 4
        for (int c = 0; c < 64; c++) {
            u64 vd[8];
            #pragma unroll
            for (int i = 0; i < 8; i++) vd[i] = dup2(sV[(ty * 8 + i) * 68 + c]);
            u64 wp[4];
            #pragma unroll
            for (int j = 0; j < 4; j++) wp[j] = *(const u64*)&Wb[c * 66 + d0 + 2 * j];
            #pragma unroll
            for (int i = 0; i < 8; i++)
                #pragma unroll
                for (int j = 0; j < 4; j++) ffma2(acc[i][j], vd[i], wp[j]);
        }

        // bias, LN (row-wise to cap registers), store
        float* dst = isK ? sK : sU;
        #pragma unroll
        for (int i = 0; i < 8; i++) {
            float q8[8];
            #pragma unroll
            for (int j = 0; j < 4; j++) {
                add2(acc[i][j], biasP[j]);
                up2(acc[i][j], q8[2 * j], q8[2 * j + 1]);
            }
            float s = 0.f, s2 = 0.f;
            #pragma unroll
            for (int k = 0; k < 8; k++) { s += q8[k]; s2 += q8[k] * q8[k]; }
            #pragma unroll
            for (int o = 1; o < 8; o <<= 1) {
                s  += __shfl_xor_sync(0xffffffffu, s,  o);
                s2 += __shfl_xor_sync(0xffffffffu, s2, o);
            }
            if (isK) {
                float mu  = s * (1.0f / 64.0f);
                float var = fmaxf(s2 * (1.0f / 64.0f) - mu * mu, 0.0f);
                float inv = rsqrtf(var + 1e-5f);
                #pragma unroll
                for (int k = 0; k < 8; k++)
                    q8[k] = (q8[k] - mu) * inv * lw8[k] + lb8[k];
            }
            #pragma unroll
            for (int j = 0; j < 4; j++)
                *(u64*)&dst[(ty * 8 + i) * 68 + d0 + 2 * j] = pk2(q8[2 * j], q8[2 * j + 1]);
        }
        __syncthreads();

        // ---- outer: group g handles tokens [g*32, g*32+32); 8d x 8e per thread
        #pragma unroll 2
        for (int t = g * 32; t < g * 32 + 32; t++) {
            u64 kd[8];
            #pragma unroll
            for (int i = 0; i < 8; i++) kd[i] = dup2(sK[t * 68 + gy * 8 + i]);
            u64 uq[4];
            #pragma unroll
            for (int j = 0; j < 4; j++) uq[j] = *(const u64*)&sU[t * 68 + gx * 8 + 2 * j];
            #pragma unroll
            for (int i = 0; i < 8; i++)
                #pragma unroll
                for (int j = 0; j < 4; j++) ffma2(kvacc[i][j], kd[i], uq[j]);
        }
        __syncthreads();
    }

    float* kvp = &g_KV[(b * H_ + h) * 4096];
    #pragma unroll
    for (int i = 0; i < 8; i++)
        #pragma unroll
        for (int j = 0; j < 4; j++) {
            float lo, hi;
            up2(kvacc[i][j], lo, hi);
            atomicAdd(&kvp[(gy * 8 + i) * 64 + gx * 8 + 2 * j],     lo);
            atomicAdd(&kvp[(gy * 8 + i) * 64 + gx * 8 + 2 * j + 1], hi);
        }
}

// ---------------------------------------------------------------------------
// Kernel 2: fold G[b,h,d,c] = sum_e KV[b,h,d,e] * o_w[c, h*64+e]  (tiny)
// ---------------------------------------------------------------------------
__global__ __launch_bounds__(256) void fold_kernel(const float* __restrict__ ow)
{
    const int h = blockIdx.x, b = blockIdx.y, tid = threadIdx.x;
    __shared__ __align__(16) float sKVt[64][64];  // [e][d]
    __shared__ __align__(16) float sOw[64][64];   // [e][c]

    const float* kvp = &g_KV[(b * H_ + h) * 4096];
    for (int i = tid; i < 4096; i += 256) {
        int d = i >> 6, e = i & 63;
        sKVt[e][d] = kvp[d * 64 + e];
    }
    for (int i = tid; i < 4096; i += 256) {
        int c = i >> 6, e = i & 63;
        sOw[e][c] = ow[c * HD_ + h * 64 + e];
    }
    __syncthreads();

    const int d0 = (tid >> 4) * 4, c0 = (tid & 15) * 4;
    float acc[16];
    #pragma unroll
    for (int i = 0; i < 16; i++) acc[i] = 0.0f;
    #pragma unroll 16
    for (int e = 0; e < 64; e++) {
        float4 kk = *(const float4*)&sKVt[e][d0];
        float4 cc = *(const float4*)&sOw[e][c0];
        acc[ 0] = fmaf(kk.x, cc.x, acc[ 0]); acc[ 1] = fmaf(kk.x, cc.y, acc[ 1]);
        acc[ 2] = fmaf(kk.x, cc.z, acc[ 2]); acc[ 3] = fmaf(kk.x, cc.w, acc[ 3]);
        acc[ 4] = fmaf(kk.y, cc.x, acc[ 4]); acc[ 5] = fmaf(kk.y, cc.y, acc[ 5]);
        acc[ 6] = fmaf(kk.y, cc.z, acc[ 6]); acc[ 7] = fmaf(kk.y, cc.w, acc[ 7]);
        acc[ 8] = fmaf(kk.z, cc.x, acc[ 8]); acc[ 9] = fmaf(kk.z, cc.y, acc[ 9]);
        acc[10] = fmaf(kk.z, cc.z, acc[10]); acc[11] = fmaf(kk.z, cc.w, acc[11]);
        acc[12] = fmaf(kk.w, cc.x, acc[12]); acc[13] = fmaf(kk.w, cc.y, acc[13]);
        acc[14] = fmaf(kk.w, cc.z, acc[14]); acc[15] = fmaf(kk.w, cc.w, acc[15]);
    }

    float* gp = &g_G[(b * H_ + h) * 4096];
    #pragma unroll
    for (int i = 0; i < 4; i++)
        #pragma unroll
        for (int j = 0; j < 4; j++)
            gp[(d0 + i) * 64 + c0 + j] = acc[i * 4 + j];
}

// ---------------------------------------------------------------------------
// Kernel 3: grid (32 chunks, B) = 128 blocks, 256 thr, 256 tokens/block.
// Head-pairs fused (128 combined dims); per-half [128t x 128d] proj 8x8;
// QG 8t x 4c per thread.
// smem (floats): sWaT[64c][66] @0 | sWbT @4228 | sV[256t][68] @8452 |
//   sQ[128t][136] @25860 | sGt[128d][68] @43268 |
//   sQb @51972(128) sLw @52100 sLb @52228 sOb @52356(64)
// ---------------------------------------------------------------------------
#define QOUT_SMEM_F 52420
#define QOUT_SMEM_BYTES (QOUT_SMEM_F * 4)

__global__ __launch_bounds__(256, 1) void qout_kernel(
    const float* __restrict__ v,
    const float* __restrict__ Wq, const float* __restrict__ qb,
    const float* __restrict__ lnw, const float* __restrict__ lnb,
    const float* __restrict__ ob,
    float* __restrict__ out)
{
    extern __shared__ float sm[];
    float* sWaT = sm;
    float* sWbT = sm + 4228;
    float* sV   = sm + 8452;
    float* sQ   = sm + 25860;   // [t][136], combined 128 dims
    float* sGt  = sm + 43268;   // [d'][68]
    float* sQb  = sm + 51972;
    float* sLw  = sm + 52100;
    float* sLb  = sm + 52228;
    float* sOb  = sm + 52356;

    const int chunk = blockIdx.x, b = blockIdx.y, tid = threadIdx.x;
    const int ty = tid >> 4, tx = tid & 15;
    const int D0  = tx * 8;          // combined dim base
    const int d0h = (tx & 7) * 8;    // within-head dim base

    const int n_base = b * N_ + chunk * 256;

    for (int i = tid; i < 4096; i += 256) {
        int t = i >> 4, c4 = (i & 15) * 4;
        *(float4*)&sV[t * 68 + c4] = *(const float4*)&v[(n_base + t) * 64 + c4];
    }
    if (tid < 64) sOb[tid] = ob[tid];

    u64 oacc[2][8][2];
    #pragma unroll
    for (int hf = 0; hf < 2; hf++)
        #pragma unroll
        for (int i = 0; i < 8; i++)
            #pragma unroll
            for (int j = 0; j < 2; j++) oacc[hf][i][j] = 0ull;

    for (int hp = 0; hp < 4; hp++) {
        __syncthreads();   // prev QG done with sQ/sGt; covers sV fill at hp=0
        for (int i = tid; i < 8192; i += 256) {
            int head = i >> 12, r = i & 4095, d = r >> 6, c = r & 63;
            (head ? sWbT : sWaT)[c * 66 + d] = Wq[((hp * 2 + head) * 64 + d) * 64 + c];
        }
        for (int i = tid; i < 8192; i += 256) {
            int dp = i >> 6, c = i & 63;
            sGt[dp * 68 + c] = g_G[(b * H_ + hp * 2 + (dp >> 6)) * 4096 + (dp & 63) * 64 + c];
        }
        if (tid < 128) {
            int head = tid >> 6, dd = tid & 63;
            sQb[tid] = qb[(hp * 2 + head) * 64 + dd];
            sLw[tid] = lnw[(hp * 2 + head) * 64 + dd];
            sLb[tid] = lnb[(hp * 2 + head) * 64 + dd];
        }
        __syncthreads();

        const float* Wb2 = (tx < 8) ? sWaT : sWbT;
        u64 biasP[4];
        float lw8[8], lb8[8];
        #pragma unroll
        for (int j = 0; j < 4; j++) biasP[j] = *(const u64*)&sQb[D0 + 2 * j];
        #pragma unroll
        for (int k = 0; k < 8; k++) { lw8[k] = sLw[D0 + k]; lb8[k] = sLb[D0 + k]; }

        for (int half = 0; half < 2; half++) {
            // ---- proj Q for tokens half*128 + ty*8..+7, dims D0..D0+7
            u64 acc[8][4];
            #pragma unroll
            for (int i = 0; i < 8; i++)
                #pragma unroll
                for (int j = 0; j < 4; j++) acc[i][j] = 0ull;

            #pragma unroll 4
            for (int c = 0; c < 64; c++) {
                u64 vd[8];
                #pragma unroll
                for (int i = 0; i < 8; i++)
                    vd[i] = dup2(sV[(half * 128 + ty * 8 + i) * 68 + c]);
                u64 wp[4];
                #pragma unroll
                for (int j = 0; j < 4; j++) wp[j] = *(const u64*)&Wb2[c * 66 + d0h + 2 * j];
                #pragma unroll
                for (int i = 0; i < 8; i++)
                    #pragma unroll
                    for (int j = 0; j < 4; j++) ffma2(acc[i][j], vd[i], wp[j]);
            }

            __syncthreads();   // prior QG readers of sQ done before overwrite
            #pragma unroll
            for (int i = 0; i < 8; i++) {
                float q8[8];
                #pragma unroll
                for (int j = 0; j < 4; j++) {
                    add2(acc[i][j], biasP[j]);
                    up2(acc[i][j], q8[2 * j], q8[2 * j + 1]);
                }
                float s = 0.f, s2 = 0.f;
                #pragma unroll
                for (int k = 0; k < 8; k++) { s += q8[k]; s2 += q8[k] * q8[k]; }
                #pragma unroll
                for (int o = 1; o < 8; o <<= 1) {
                    s  += __shfl_xor_sync(0xffffffffu, s,  o);
                    s2 += __shfl_xor_sync(0xffffffffu, s2, o);
                }
                float mu  = s * (1.0f / 64.0f);
                float var = fmaxf(s2 * (1.0f / 64.0f) - mu * mu, 0.0f);
                float inv = rsqrtf(var + 1e-5f);
                #pragma unroll
                for (int k = 0; k < 8; k++)
                    q8[k] = (q8[k] - mu) * inv * lw8[k] + lb8[k];
                #pragma unroll
                for (int j = 0; j < 4; j++)
                    *(u64*)&sQ[(ty * 8 + i) * 136 + D0 + 2 * j] = pk2(q8[2 * j], q8[2 * j + 1]);
            }
            __syncthreads();

            // ---- QG: out[half][8t x 4c] += Q[t][d'] * G[d'][c], d' 0..127
            #pragma unroll 2
            for (int d = 0; d < 128; d++) {
                u64 qd[8];
                #pragma unroll
                for (int i = 0; i < 8; i++) qd[i] = dup2(sQ[(ty * 8 + i) * 136 + d]);
                u64 gp[2];
                #pragma unroll
                for (int j = 0; j < 2; j++) gp[j] = *(const u64*)&sGt[d * 68 + tx * 4 + 2 * j];
                #pragma unroll
                for (int i = 0; i < 8; i++)
                    #pragma unroll
                    for (int j = 0; j < 2; j++) ffma2(oacc[half][i][j], qd[i], gp[j]);
            }
        }
    }

    const float inv_n = 1.0f / (float)N_;
    float ob4[4];
    #pragma unroll
    for (int jj = 0; jj < 4; jj++) ob4[jj] = sOb[tx * 4 + jj];
    #pragma unroll
    for (int half = 0; half < 2; half++)
        #pragma unroll
        for (int i = 0; i < 8; i++) {
            float o0, o1, o2, o3;
            up2(oacc[half][i][0], o0, o1);
            up2(oacc[half][i][1], o2, o3);
            float4 o;
            o.x = (o0 + ob4[0]) * inv_n;
            o.y = (o1 + ob4[1]) * inv_n;
            o.z = (o2 + ob4[2]) * inv_n;
            o.w = (o3 + ob4[3]) * inv_n;
            *(float4*)&out[(n_base + half * 128 + ty * 8 + i) * 64 + tx * 4] = o;
        }
}

// ---------------------------------------------------------------------------
extern "C" void kernel_launch(void* const* d_in, const int* in_sizes, int n_in,
                              void* d_out, int out_size)
{
    const float* v     = (const float*)d_in[0];
    const float* Wq_w  = (const float*)d_in[1];
    const float* Wq_b  = (const float*)d_in[2];
    const float* Wk_w  = (const float*)d_in[3];
    const float* Wk_b  = (const float*)d_in[4];
    const float* Wv_w  = (const float*)d_in[5];
    const float* Wv_b  = (const float*)d_in[6];
    const float* lnq_w = (const float*)d_in[7];
    const float* lnq_b = (const float*)d_in[8];
    const float* lnk_w = (const float*)d_in[9];
    const float* lnk_b = (const float*)d_in[10];
    const float* o_w   = (const float*)d_in[11];
    const float* o_b   = (const float*)d_in[12];
    float* out = (float*)d_out;

    static bool attr_done = false;
    if (!attr_done) {
        cudaFuncSetAttribute(kv_kernel,   cudaFuncAttributeMaxDynamicSharedMemorySize, KV_SMEM_BYTES);
        cudaFuncSetAttribute(qout_kernel, cudaFuncAttributeMaxDynamicSharedMemorySize, QOUT_SMEM_BYTES);
        attr_done = true;
    }

    // 512 * 256 = 131072 threads covers all B_*H_*4096 = 131072 elements.
    zero_kv_kernel<<<512, 256>>>();
    kv_kernel<<<dim3(4, H_, B_), 256, KV_SMEM_BYTES>>>(v, Wk_w, Wk_b, Wv_w, Wv_b, lnk_w, lnk_b);
    fold_kernel<<<dim3(H_, B_), 256>>>(o_w);
    qout_kernel<<<dim3(32, B_), 256, QOUT_SMEM_BYTES>>>(v, Wq_w, Wq_b, lnq_w, lnq_b, o_b, out);
}